// round 1
// baseline (speedup 1.0000x reference)
#include <cuda_runtime.h>
#include <cuda_bf16.h>
#include <stdint.h>

#define N_NODES 100000
#define N_EDGES 640000
#define HID     128
#define EPS     1e-6f

// Scratch (allocation-free rule: __device__ globals)
__device__ float g_c1[HID];
__device__ float g_c2[HID];
__device__ float g_cconst;
__device__ int   g_is64;
__device__ float g_alpha[N_NODES];
__device__ float g_beta[N_NODES];
__device__ float g_n[N_NODES];

// ---------------------------------------------------------------------------
// Detect whether the edge buffer is int64 or int32 (jax x64-disabled trap).
// If data is int32 pairs, reading 8 bytes as int64 gives src + (dst<<32),
// which is >= 2^32 unless dst==0 (prob 1e-5 per element). Check 8 values.
// ---------------------------------------------------------------------------
__global__ void k_detect(const long long* __restrict__ e) {
    if (threadIdx.x == 0) {
        bool is64 = true;
        #pragma unroll
        for (int i = 0; i < 8; ++i) {
            long long v = e[i];
            if (v < 0 || v >= (long long)N_NODES) is64 = false;
        }
        g_is64 = is64 ? 1 : 0;
    }
}

// ---------------------------------------------------------------------------
// c1 = att_w[0:128] @ W,  c2 = att_w[128:256] @ W,  cconst = (aw1+aw2)·b
// ---------------------------------------------------------------------------
__global__ void k_prep(const float* __restrict__ W,
                       const float* __restrict__ b,
                       const float* __restrict__ att_w) {
    int k = threadIdx.x;  // 0..127
    float c1 = 0.f, c2 = 0.f;
    #pragma unroll 8
    for (int j = 0; j < HID; ++j) {
        float w = W[j * HID + k];
        c1 = fmaf(att_w[j],        w, c1);
        c2 = fmaf(att_w[HID + j],  w, c2);
    }
    g_c1[k] = c1;
    g_c2[k] = c2;
    if (k == 0) {
        float cc = 0.f;
        for (int j = 0; j < HID; ++j) cc += (att_w[j] + att_w[HID + j]) * b[j];
        g_cconst = cc;
    }
}

// ---------------------------------------------------------------------------
// Per-node scalars: alpha[i] = x[i]·c1, beta[i] = x[i]·c2. One warp per node,
// float4 per lane (32*4 = 128). Also zeroes the accumulator n.
// ---------------------------------------------------------------------------
__global__ void k_node(const float* __restrict__ x) {
    int gwarp = (blockIdx.x * blockDim.x + threadIdx.x) >> 5;
    int lane  = threadIdx.x & 31;
    if (gwarp >= N_NODES) return;

    float4 xv = reinterpret_cast<const float4*>(x + (size_t)gwarp * HID)[lane];
    float4 c1 = reinterpret_cast<const float4*>(g_c1)[lane];
    float4 c2 = reinterpret_cast<const float4*>(g_c2)[lane];

    float a = xv.x * c1.x + xv.y * c1.y + xv.z * c1.z + xv.w * c1.w;
    float bta = xv.x * c2.x + xv.y * c2.y + xv.z * c2.z + xv.w * c2.w;

    #pragma unroll
    for (int o = 16; o > 0; o >>= 1) {
        a   += __shfl_xor_sync(0xFFFFFFFFu, a,   o);
        bta += __shfl_xor_sync(0xFFFFFFFFu, bta, o);
    }
    if (lane == 0) {
        g_alpha[gwarp] = a;
        g_beta[gwarp]  = bta;
        g_n[gwarp]     = 0.f;
    }
}

// ---------------------------------------------------------------------------
// Per-edge: score = alpha[src] + beta[dst] + cconst; a = exp(leaky_relu(score))
// n[dst] += a  (atomic, compiles to RED — no return needed)
// ---------------------------------------------------------------------------
__global__ void k_edges(const void* __restrict__ e_raw) {
    int i = blockIdx.x * blockDim.x + threadIdx.x;
    if (i >= N_EDGES) return;

    int src, dst;
    if (g_is64) {
        longlong2 ed = reinterpret_cast<const longlong2*>(e_raw)[i];
        src = (int)ed.x; dst = (int)ed.y;
    } else {
        int2 ed = reinterpret_cast<const int2*>(e_raw)[i];
        src = ed.x; dst = ed.y;
    }
    float s = g_alpha[src] + g_beta[dst] + g_cconst;
    s = (s >= 0.f) ? s : 0.2f * s;
    atomicAdd(&g_n[dst], expf(s));
}

// ---------------------------------------------------------------------------
// Per-node output: denom = (n==0)?1:n; y = relu(x/denom) + x; rmsnorm(y).
// One warp per node, float4 per lane.
// ---------------------------------------------------------------------------
__global__ void k_out(const float* __restrict__ x,
                      const float* __restrict__ norm_w,
                      const float* __restrict__ norm_b,
                      float* __restrict__ out) {
    int gwarp = (blockIdx.x * blockDim.x + threadIdx.x) >> 5;
    int lane  = threadIdx.x & 31;
    if (gwarp >= N_NODES) return;

    float n = g_n[gwarp];
    float denom = (n == 0.f) ? 1.f : n;
    float inv = 1.f / denom;

    float4 xv = reinterpret_cast<const float4*>(x + (size_t)gwarp * HID)[lane];

    float4 y;
    y.x = fmaxf(xv.x * inv, 0.f) + xv.x;
    y.y = fmaxf(xv.y * inv, 0.f) + xv.y;
    y.z = fmaxf(xv.z * inv, 0.f) + xv.z;
    y.w = fmaxf(xv.w * inv, 0.f) + xv.w;

    float ss = y.x * y.x + y.y * y.y + y.z * y.z + y.w * y.w;
    #pragma unroll
    for (int o = 16; o > 0; o >>= 1)
        ss += __shfl_xor_sync(0xFFFFFFFFu, ss, o);

    float inv_rms = rsqrtf(ss * (1.f / (float)HID) + EPS);

    float4 w4 = reinterpret_cast<const float4*>(norm_w)[lane];
    float4 b4 = reinterpret_cast<const float4*>(norm_b)[lane];

    float4 o4;
    o4.x = fmaf(w4.x, y.x * inv_rms, b4.x);
    o4.y = fmaf(w4.y, y.y * inv_rms, b4.y);
    o4.z = fmaf(w4.z, y.z * inv_rms, b4.z);
    o4.w = fmaf(w4.w, y.w * inv_rms, b4.w);

    reinterpret_cast<float4*>(out + (size_t)gwarp * HID)[lane] = o4;
}

// ---------------------------------------------------------------------------
extern "C" void kernel_launch(void* const* d_in, const int* in_sizes, int n_in,
                              void* d_out, int out_size) {
    const float* x      = (const float*)d_in[0];
    const float* W      = (const float*)d_in[1];
    const float* b      = (const float*)d_in[2];
    const float* att_w  = (const float*)d_in[3];
    const float* norm_w = (const float*)d_in[4];
    const float* norm_b = (const float*)d_in[5];
    const void*  e      = d_in[6];
    float* out          = (float*)d_out;

    (void)in_sizes; (void)n_in; (void)out_size;

    k_detect<<<1, 32>>>((const long long*)e);
    k_prep<<<1, HID>>>(W, b, att_w);

    {   // one warp per node
        int threads = 256;
        int warps_needed = N_NODES;
        int blocks = (warps_needed * 32 + threads - 1) / threads;
        k_node<<<blocks, threads>>>(x);
    }
    {
        int threads = 256;
        int blocks = (N_EDGES + threads - 1) / threads;
        k_edges<<<blocks, threads>>>(e);
    }
    {
        int threads = 256;
        int blocks = (N_NODES * 32 + threads - 1) / threads;
        k_out<<<blocks, threads>>>(x, norm_w, norm_b, out);
    }
}

// round 2
// speedup vs baseline: 1.9890x; 1.9890x over previous
#include <cuda_runtime.h>
#include <cuda_bf16.h>
#include <stdint.h>

#define N_NODES 100000
#define N_EDGES 640000
#define HID     128
#define EPS     1e-6f

// Scratch (allocation-free rule: __device__ globals)
__device__ float g_c1[HID];
__device__ float g_c2[HID];
__device__ float g_cconst;
__device__ int   g_is64;
__device__ float g_alpha[N_NODES];
__device__ float g_beta[N_NODES];
__device__ float g_n[N_NODES];

// ---------------------------------------------------------------------------
// Fused prep + dtype detection. 1 block, 512 threads.
// c1[k] = sum_j att_w[j]     * W[j*128+k]
// c2[k] = sum_j att_w[128+j] * W[j*128+k]
// 4-way split over j (part = tid>>7), smem reduce. cconst + detection after.
// ---------------------------------------------------------------------------
__global__ void k_prep(const float* __restrict__ W,
                       const float* __restrict__ b,
                       const float* __restrict__ att_w,
                       const long long* __restrict__ e64) {
    __shared__ float s1[512];
    __shared__ float s2[512];
    int tid  = threadIdx.x;
    int k    = tid & 127;
    int part = tid >> 7;          // 0..3

    float c1 = 0.f, c2 = 0.f;
    int j0 = part * 32;
    #pragma unroll 8
    for (int j = j0; j < j0 + 32; ++j) {
        float w = W[j * HID + k];           // coalesced across k
        c1 = fmaf(att_w[j],       w, c1);
        c2 = fmaf(att_w[HID + j], w, c2);
    }
    s1[tid] = c1; s2[tid] = c2;
    __syncthreads();

    if (part == 0) {
        g_c1[k] = s1[k] + s1[k + 128] + s1[k + 256] + s1[k + 384];
        g_c2[k] = s2[k] + s2[k + 128] + s2[k + 256] + s2[k + 384];
    }
    __syncthreads();

    if (tid < 128) s1[tid] = (att_w[tid] + att_w[HID + tid]) * b[tid];
    __syncthreads();

    if (tid == 0) {
        float cc = 0.f;
        #pragma unroll 8
        for (int j = 0; j < HID; ++j) cc += s1[j];
        g_cconst = cc;

        // int64-vs-int32 detection (jax x64-disabled trap): int32 pairs read
        // as int64 give src + (dst<<32) >= 2^32 unless dst==0.
        bool is64 = true;
        #pragma unroll
        for (int i = 0; i < 8; ++i) {
            long long v = e64[i];
            if (v < 0 || v >= (long long)N_NODES) is64 = false;
        }
        g_is64 = is64 ? 1 : 0;
    }
}

// ---------------------------------------------------------------------------
// Per-node scalars: alpha[i] = x[i]·c1, beta[i] = x[i]·c2. One warp per node,
// float4 per lane. Also zeroes the accumulator n.
// ---------------------------------------------------------------------------
__global__ void k_node(const float* __restrict__ x) {
    int gwarp = (blockIdx.x * blockDim.x + threadIdx.x) >> 5;
    int lane  = threadIdx.x & 31;
    if (gwarp >= N_NODES) return;

    float4 xv = __ldg(&reinterpret_cast<const float4*>(x + (size_t)gwarp * HID)[lane]);
    float4 c1 = reinterpret_cast<const float4*>(g_c1)[lane];
    float4 c2 = reinterpret_cast<const float4*>(g_c2)[lane];

    float a   = xv.x * c1.x + xv.y * c1.y + xv.z * c1.z + xv.w * c1.w;
    float bta = xv.x * c2.x + xv.y * c2.y + xv.z * c2.z + xv.w * c2.w;

    #pragma unroll
    for (int o = 16; o > 0; o >>= 1) {
        a   += __shfl_xor_sync(0xFFFFFFFFu, a,   o);
        bta += __shfl_xor_sync(0xFFFFFFFFu, bta, o);
    }
    if (lane == 0) {
        g_alpha[gwarp] = a;
        g_beta[gwarp]  = bta;
        g_n[gwarp]     = 0.f;
    }
}

// ---------------------------------------------------------------------------
// Per-edge: score = alpha[src] + beta[dst] + cconst; n[dst] += exp(lrelu(score))
// 4 edges/thread, strided for coalescing; batched loads give MLP ~8 on the
// L2-resident alpha/beta gathers. atomicAdd w/o return compiles to RED.
// ---------------------------------------------------------------------------
#define EDGE_U 4
#define EDGE_TOT (N_EDGES / EDGE_U)   // 160000 threads

__global__ void k_edges(const void* __restrict__ e_raw) {
    int t = blockIdx.x * blockDim.x + threadIdx.x;
    if (t >= EDGE_TOT) return;

    int s[EDGE_U], d[EDGE_U];
    if (g_is64) {
        const longlong2* e = (const longlong2*)e_raw;
        #pragma unroll
        for (int u = 0; u < EDGE_U; ++u) {
            longlong2 v = __ldg(&e[t + u * EDGE_TOT]);
            s[u] = (int)v.x; d[u] = (int)v.y;
        }
    } else {
        const int2* e = (const int2*)e_raw;
        #pragma unroll
        for (int u = 0; u < EDGE_U; ++u) {
            int2 v = __ldg(&e[t + u * EDGE_TOT]);
            s[u] = v.x; d[u] = v.y;
        }
    }

    float a[EDGE_U], bb[EDGE_U];
    #pragma unroll
    for (int u = 0; u < EDGE_U; ++u) {
        a[u]  = __ldg(&g_alpha[s[u]]);
        bb[u] = __ldg(&g_beta[d[u]]);
    }

    float cc = g_cconst;
    #pragma unroll
    for (int u = 0; u < EDGE_U; ++u) {
        float sc = a[u] + bb[u] + cc;
        sc = (sc >= 0.f) ? sc : 0.2f * sc;
        atomicAdd(&g_n[d[u]], __expf(sc));
    }
}

// ---------------------------------------------------------------------------
// Per-node output: denom = (n==0)?1:n; y = relu(x/denom) + x; rmsnorm(y).
// One warp per node, float4 per lane, streaming stores.
// ---------------------------------------------------------------------------
__global__ void k_out(const float* __restrict__ x,
                      const float* __restrict__ norm_w,
                      const float* __restrict__ norm_b,
                      float* __restrict__ out) {
    int gwarp = (blockIdx.x * blockDim.x + threadIdx.x) >> 5;
    int lane  = threadIdx.x & 31;
    if (gwarp >= N_NODES) return;

    float n = g_n[gwarp];
    float inv = (n == 0.f) ? 1.f : __frcp_rn(n);

    float4 xv = __ldg(&reinterpret_cast<const float4*>(x + (size_t)gwarp * HID)[lane]);

    float4 y;
    y.x = fmaxf(xv.x * inv, 0.f) + xv.x;
    y.y = fmaxf(xv.y * inv, 0.f) + xv.y;
    y.z = fmaxf(xv.z * inv, 0.f) + xv.z;
    y.w = fmaxf(xv.w * inv, 0.f) + xv.w;

    float ss = y.x * y.x + y.y * y.y + y.z * y.z + y.w * y.w;
    #pragma unroll
    for (int o = 16; o > 0; o >>= 1)
        ss += __shfl_xor_sync(0xFFFFFFFFu, ss, o);

    float inv_rms = rsqrtf(ss * (1.f / (float)HID) + EPS);

    float4 w4 = __ldg(&reinterpret_cast<const float4*>(norm_w)[lane]);
    float4 b4 = __ldg(&reinterpret_cast<const float4*>(norm_b)[lane]);

    float4 o4;
    o4.x = fmaf(w4.x, y.x * inv_rms, b4.x);
    o4.y = fmaf(w4.y, y.y * inv_rms, b4.y);
    o4.z = fmaf(w4.z, y.z * inv_rms, b4.z);
    o4.w = fmaf(w4.w, y.w * inv_rms, b4.w);

    __stcs(&reinterpret_cast<float4*>(out + (size_t)gwarp * HID)[lane], o4);
}

// ---------------------------------------------------------------------------
extern "C" void kernel_launch(void* const* d_in, const int* in_sizes, int n_in,
                              void* d_out, int out_size) {
    const float* x      = (const float*)d_in[0];
    const float* W      = (const float*)d_in[1];
    const float* b      = (const float*)d_in[2];
    const float* att_w  = (const float*)d_in[3];
    const float* norm_w = (const float*)d_in[4];
    const float* norm_b = (const float*)d_in[5];
    const void*  e      = d_in[6];
    float* out          = (float*)d_out;

    (void)in_sizes; (void)n_in; (void)out_size;

    k_prep<<<1, 512>>>(W, b, att_w, (const long long*)e);

    {   // one warp per node
        int threads = 256;
        int blocks = (N_NODES * 32 + threads - 1) / threads;
        k_node<<<blocks, threads>>>(x);
    }
    {
        int threads = 256;
        int blocks = (EDGE_TOT + threads - 1) / threads;
        k_edges<<<blocks, threads>>>(e);
    }
    {
        int threads = 256;
        int blocks = (N_NODES * 32 + threads - 1) / threads;
        k_out<<<blocks, threads>>>(x, norm_w, norm_b, out);
    }
}

// round 3
// speedup vs baseline: 2.2374x; 1.1249x over previous
#include <cuda_runtime.h>
#include <cuda_bf16.h>
#include <stdint.h>

#define N_NODES 100000
#define N_EDGES 640000
#define HID     128
#define EPS     1e-6f

// Scratch (allocation-free rule: __device__ globals)
__device__ float g_c1[HID];
__device__ float g_c2[HID];
__device__ float g_cconst;
__device__ int   g_is64;
__device__ float g_alpha[N_NODES];
__device__ float g_beta[N_NODES];
__device__ float g_n[N_NODES];

// ---------------------------------------------------------------------------
// Fused prep + dtype detection. 1 block, 512 threads.
// c1[k] = sum_j att_w[j] * W[j*128+k],  c2[k] = sum_j att_w[128+j] * W[j*128+k]
// ---------------------------------------------------------------------------
__global__ void k_prep(const float* __restrict__ W,
                       const float* __restrict__ b,
                       const float* __restrict__ att_w,
                       const long long* __restrict__ e64) {
    __shared__ float s1[512];
    __shared__ float s2[512];
    int tid  = threadIdx.x;
    int k    = tid & 127;
    int part = tid >> 7;          // 0..3

    float c1 = 0.f, c2 = 0.f;
    int j0 = part * 32;
    #pragma unroll 8
    for (int j = j0; j < j0 + 32; ++j) {
        float w = W[j * HID + k];           // coalesced across k
        c1 = fmaf(att_w[j],       w, c1);
        c2 = fmaf(att_w[HID + j], w, c2);
    }
    s1[tid] = c1; s2[tid] = c2;
    __syncthreads();

    if (part == 0) {
        g_c1[k] = s1[k] + s1[k + 128] + s1[k + 256] + s1[k + 384];
        g_c2[k] = s2[k] + s2[k + 128] + s2[k + 256] + s2[k + 384];
    }
    __syncthreads();

    if (tid < 128) s1[tid] = (att_w[tid] + att_w[HID + tid]) * b[tid];
    __syncthreads();

    if (tid == 0) {
        float cc = 0.f;
        #pragma unroll 8
        for (int j = 0; j < HID; ++j) cc += s1[j];
        g_cconst = cc;

        // int64-vs-int32 detection (jax x64-disabled trap): int32 pairs read
        // as int64 give src + (dst<<32) >= 2^32 unless dst==0.
        bool is64 = true;
        #pragma unroll
        for (int i = 0; i < 8; ++i) {
            long long v = e64[i];
            if (v < 0 || v >= (long long)N_NODES) is64 = false;
        }
        g_is64 = is64 ? 1 : 0;
    }
}

// ---------------------------------------------------------------------------
// Per-node scalars, TWO nodes per warp (half-warp layout):
//   lanes 0-15 -> node 2w,  lanes 16-31 -> node 2w+1
//   lane owns float4 columns hl and hl+16 of its node's row.
// Butterfly over offsets {8,4,2,1} reduces within each half independently.
// ---------------------------------------------------------------------------
__global__ void k_node(const float* __restrict__ x) {
    int gw   = (blockIdx.x * blockDim.x + threadIdx.x) >> 5;
    int lane = threadIdx.x & 31;
    int half = lane >> 4;
    int hl   = lane & 15;
    int node = gw * 2 + half;
    if (node >= N_NODES) return;

    const float4* xr = reinterpret_cast<const float4*>(x + (size_t)node * HID);
    float4 v0 = __ldg(&xr[hl]);
    float4 v1 = __ldg(&xr[hl + 16]);

    const float4* C1 = reinterpret_cast<const float4*>(g_c1);
    const float4* C2 = reinterpret_cast<const float4*>(g_c2);
    float4 c10 = C1[hl], c11 = C1[hl + 16];
    float4 c20 = C2[hl], c21 = C2[hl + 16];

    float a = v0.x*c10.x + v0.y*c10.y + v0.z*c10.z + v0.w*c10.w
            + v1.x*c11.x + v1.y*c11.y + v1.z*c11.z + v1.w*c11.w;
    float bt = v0.x*c20.x + v0.y*c20.y + v0.z*c20.z + v0.w*c20.w
             + v1.x*c21.x + v1.y*c21.y + v1.z*c21.z + v1.w*c21.w;

    #pragma unroll
    for (int o = 8; o > 0; o >>= 1) {
        a  += __shfl_xor_sync(0xFFFFFFFFu, a,  o);
        bt += __shfl_xor_sync(0xFFFFFFFFu, bt, o);
    }
    if (hl == 0) {
        g_alpha[node] = a;
        g_beta[node]  = bt;
        g_n[node]     = 0.f;
    }
}

// ---------------------------------------------------------------------------
// Per-edge: n[dst] += exp(leaky_relu(alpha[src] + beta[dst] + cconst)).
// 8 edges/thread, strided for coalescing -> 16 outstanding L2 gathers.
// ---------------------------------------------------------------------------
#define EDGE_U 8
#define EDGE_TOT (N_EDGES / EDGE_U)   // 80000 threads

__global__ void k_edges(const void* __restrict__ e_raw) {
    int t = blockIdx.x * blockDim.x + threadIdx.x;
    if (t >= EDGE_TOT) return;

    int s[EDGE_U], d[EDGE_U];
    if (g_is64) {
        const longlong2* e = (const longlong2*)e_raw;
        #pragma unroll
        for (int u = 0; u < EDGE_U; ++u) {
            longlong2 v = __ldg(&e[t + u * EDGE_TOT]);
            s[u] = (int)v.x; d[u] = (int)v.y;
        }
    } else {
        const int2* e = (const int2*)e_raw;
        #pragma unroll
        for (int u = 0; u < EDGE_U; ++u) {
            int2 v = __ldg(&e[t + u * EDGE_TOT]);
            s[u] = v.x; d[u] = v.y;
        }
    }

    float a[EDGE_U], bb[EDGE_U];
    #pragma unroll
    for (int u = 0; u < EDGE_U; ++u) {
        a[u]  = __ldg(&g_alpha[s[u]]);
        bb[u] = __ldg(&g_beta[d[u]]);
    }

    float cc = g_cconst;
    #pragma unroll
    for (int u = 0; u < EDGE_U; ++u) {
        float sc = a[u] + bb[u] + cc;
        sc = (sc >= 0.f) ? sc : 0.2f * sc;
        atomicAdd(&g_n[d[u]], __expf(sc));
    }
}

// ---------------------------------------------------------------------------
// Output, TWO nodes per warp (same half-warp layout as k_node):
// denom = (n==0)?1:n; y = relu(x/denom) + x; out = norm_w * y*inv_rms + norm_b
// ---------------------------------------------------------------------------
__global__ void k_out(const float* __restrict__ x,
                      const float* __restrict__ norm_w,
                      const float* __restrict__ norm_b,
                      float* __restrict__ out) {
    int gw   = (blockIdx.x * blockDim.x + threadIdx.x) >> 5;
    int lane = threadIdx.x & 31;
    int half = lane >> 4;
    int hl   = lane & 15;
    int node = gw * 2 + half;
    if (node >= N_NODES) return;

    float n = __ldg(&g_n[node]);
    float inv = (n == 0.f) ? 1.f : __frcp_rn(n);

    const float4* xr = reinterpret_cast<const float4*>(x + (size_t)node * HID);
    float4 v0 = __ldg(&xr[hl]);
    float4 v1 = __ldg(&xr[hl + 16]);

    float4 y0, y1;
    y0.x = fmaxf(v0.x * inv, 0.f) + v0.x;
    y0.y = fmaxf(v0.y * inv, 0.f) + v0.y;
    y0.z = fmaxf(v0.z * inv, 0.f) + v0.z;
    y0.w = fmaxf(v0.w * inv, 0.f) + v0.w;
    y1.x = fmaxf(v1.x * inv, 0.f) + v1.x;
    y1.y = fmaxf(v1.y * inv, 0.f) + v1.y;
    y1.z = fmaxf(v1.z * inv, 0.f) + v1.z;
    y1.w = fmaxf(v1.w * inv, 0.f) + v1.w;

    float ss = y0.x*y0.x + y0.y*y0.y + y0.z*y0.z + y0.w*y0.w
             + y1.x*y1.x + y1.y*y1.y + y1.z*y1.z + y1.w*y1.w;
    #pragma unroll
    for (int o = 8; o > 0; o >>= 1)
        ss += __shfl_xor_sync(0xFFFFFFFFu, ss, o);

    float inv_rms = rsqrtf(ss * (1.f / (float)HID) + EPS);

    const float4* Wn = reinterpret_cast<const float4*>(norm_w);
    const float4* Bn = reinterpret_cast<const float4*>(norm_b);
    float4 w0 = __ldg(&Wn[hl]),      b0 = __ldg(&Bn[hl]);
    float4 w1 = __ldg(&Wn[hl + 16]), b1 = __ldg(&Bn[hl + 16]);

    float4 o0, o1;
    o0.x = fmaf(w0.x, y0.x * inv_rms, b0.x);
    o0.y = fmaf(w0.y, y0.y * inv_rms, b0.y);
    o0.z = fmaf(w0.z, y0.z * inv_rms, b0.z);
    o0.w = fmaf(w0.w, y0.w * inv_rms, b0.w);
    o1.x = fmaf(w1.x, y1.x * inv_rms, b1.x);
    o1.y = fmaf(w1.y, y1.y * inv_rms, b1.y);
    o1.z = fmaf(w1.z, y1.z * inv_rms, b1.z);
    o1.w = fmaf(w1.w, y1.w * inv_rms, b1.w);

    float4* orow = reinterpret_cast<float4*>(out + (size_t)node * HID);
    __stcs(&orow[hl],      o0);
    __stcs(&orow[hl + 16], o1);
}

// ---------------------------------------------------------------------------
extern "C" void kernel_launch(void* const* d_in, const int* in_sizes, int n_in,
                              void* d_out, int out_size) {
    const float* x      = (const float*)d_in[0];
    const float* W      = (const float*)d_in[1];
    const float* b      = (const float*)d_in[2];
    const float* att_w  = (const float*)d_in[3];
    const float* norm_w = (const float*)d_in[4];
    const float* norm_b = (const float*)d_in[5];
    const void*  e      = d_in[6];
    float* out          = (float*)d_out;

    (void)in_sizes; (void)n_in; (void)out_size;

    k_prep<<<1, 512>>>(W, b, att_w, (const long long*)e);

    {   // two nodes per warp
        int warps  = (N_NODES + 1) / 2;            // 50000
        int threads = 256;
        int blocks = (warps * 32 + threads - 1) / threads;
        k_node<<<blocks, threads>>>(x);
    }
    {
        int threads = 256;
        int blocks = (EDGE_TOT + threads - 1) / threads;
        k_edges<<<blocks, threads>>>(e);
    }
    {
        int warps  = (N_NODES + 1) / 2;
        int threads = 256;
        int blocks = (warps * 32 + threads - 1) / threads;
        k_out<<<blocks, threads>>>(x, norm_w, norm_b, out);
    }
}